// round 2
// baseline (speedup 1.0000x reference)
#include <cuda_runtime.h>
#include <cuda_bf16.h>
#include <cstdint>

// Problem constants
#define E_   8
#define T_   1024
#define H_   1024
#define F_   4096
#define DL_  256
#define NTOK (E_ * T_)   // 8192

// ---------------- device scratch (static; no runtime allocation) ----------------
__device__ __nv_bfloat16 g_x_hi  [(size_t)NTOK * H_];
__device__ __nv_bfloat16 g_x_lo  [(size_t)NTOK * H_];
__device__ __nv_bfloat16 g_a_hi  [(size_t)NTOK * DL_];
__device__ __nv_bfloat16 g_a_lo  [(size_t)NTOK * DL_];
__device__ __nv_bfloat16 g_wup_hi[(size_t)E_ * F_ * DL_];
__device__ __nv_bfloat16 g_wup_lo[(size_t)E_ * F_ * DL_];
__device__ __nv_bfloat16 g_v1_hi [(size_t)E_ * F_ * H_];
__device__ __nv_bfloat16 g_v1_lo [(size_t)E_ * F_ * H_];
__device__ __nv_bfloat16 g_h_hi  [(size_t)E_ * T_ * F_];
__device__ __nv_bfloat16 g_h_lo  [(size_t)E_ * T_ * F_];
__device__ __nv_bfloat16 g_w2t_hi[(size_t)E_ * H_ * F_];
__device__ __nv_bfloat16 g_w2t_lo[(size_t)E_ * H_ * F_];

// ---------------- helpers ----------------
__device__ __forceinline__ uint32_t smem_u32(const void* p) {
    uint32_t a;
    asm("{ .reg .u64 t; cvta.to.shared.u64 t, %1; cvt.u32.u64 %0, t; }" : "=r"(a) : "l"(p));
    return a;
}

__device__ __forceinline__ void ldsm_x4(uint32_t (&r)[4], uint32_t addr) {
    asm volatile("ldmatrix.sync.aligned.m8n8.x4.shared.b16 {%0,%1,%2,%3}, [%4];"
        : "=r"(r[0]), "=r"(r[1]), "=r"(r[2]), "=r"(r[3]) : "r"(addr));
}

__device__ __forceinline__ void mma16816(float (&d)[4], const uint32_t (&a)[4],
                                         uint32_t b0, uint32_t b1) {
    asm volatile(
        "mma.sync.aligned.m16n8k16.row.col.f32.bf16.bf16.f32 "
        "{%0,%1,%2,%3}, {%4,%5,%6,%7}, {%8,%9}, {%0,%1,%2,%3};"
        : "+f"(d[0]), "+f"(d[1]), "+f"(d[2]), "+f"(d[3])
        : "r"(a[0]), "r"(a[1]), "r"(a[2]), "r"(a[3]), "r"(b0), "r"(b1));
}

__device__ __forceinline__ void cp16(uint32_t saddr, const void* g) {
    asm volatile("cp.async.cg.shared.global [%0], [%1], 16;" :: "r"(saddr), "l"(g));
}
#define CP_COMMIT() asm volatile("cp.async.commit_group;" ::: "memory")
#define CP_WAIT(N)  asm volatile("cp.async.wait_group %0;" :: "n"(N) : "memory")

__device__ __forceinline__ void split1(float v, __nv_bfloat16& h, __nv_bfloat16& l) {
    h = __float2bfloat16(v);
    l = __float2bfloat16(v - __bfloat162float(h));
}
__device__ __forceinline__ uint32_t pack_bf2(__nv_bfloat16 a, __nv_bfloat16 b) {
    __nv_bfloat162 t; t.x = a; t.y = b;
    return *reinterpret_cast<uint32_t*>(&t);
}

// ---------------- conversion kernels ----------------
// which: 0=x, 1=acts, 2=wup, 3=v1
__global__ void __launch_bounds__(256) split_convert(const float* __restrict__ src, int which, int n) {
    __nv_bfloat16 *hi, *lo;
    if      (which == 0) { hi = g_x_hi;   lo = g_x_lo; }
    else if (which == 1) { hi = g_a_hi;   lo = g_a_lo; }
    else if (which == 2) { hi = g_wup_hi; lo = g_wup_lo; }
    else                 { hi = g_v1_hi;  lo = g_v1_lo; }
    int i = (blockIdx.x * 256 + threadIdx.x) * 4;
    if (i >= n) return;
    float4 v = *reinterpret_cast<const float4*>(src + i);
    __nv_bfloat16 h0,h1,h2,h3,l0,l1,l2,l3;
    split1(v.x,h0,l0); split1(v.y,h1,l1); split1(v.z,h2,l2); split1(v.w,h3,l3);
    uint2 hv = make_uint2(pack_bf2(h0,h1), pack_bf2(h2,h3));
    uint2 lv = make_uint2(pack_bf2(l0,l1), pack_bf2(l2,l3));
    *reinterpret_cast<uint2*>(hi + i) = hv;
    *reinterpret_cast<uint2*>(lo + i) = lv;
}

// w2 [E,F,H] -> w2t [E,H,F] with split
__global__ void __launch_bounds__(256) transpose_convert_w2(const float* __restrict__ w2) {
    __shared__ float tile[32][33];
    int e = blockIdx.z;
    int f0 = blockIdx.x * 32, h0 = blockIdx.y * 32;
    int tx = threadIdx.x, ty = threadIdx.y;  // 32 x 8
#pragma unroll
    for (int r = 0; r < 4; r++) {
        int f = f0 + ty + r * 8;
        tile[ty + r * 8][tx] = w2[((size_t)e * F_ + f) * H_ + h0 + tx];
    }
    __syncthreads();
#pragma unroll
    for (int r = 0; r < 4; r++) {
        int h = h0 + ty + r * 8;
        float v = tile[tx][ty + r * 8];   // w2[f0+tx][h]
        __nv_bfloat16 hi, lo; split1(v, hi, lo);
        size_t off = ((size_t)e * H_ + h) * F_ + f0 + tx;
        g_w2t_hi[off] = hi;
        g_w2t_lo[off] = lo;
    }
}

// ---------------- GEMM machinery (mma.sync, bf16 hi/lo 3-term split) ----------------
static constexpr int SA = 72;                       // smem row stride in bf16 elems
static constexpr int TILE_BYTES = 128 * SA * 2;     // 18432 B per 128x64 tile
static constexpr int STAGE_BYTES = 4 * TILE_BYTES;  // Ah, Al, Bh, Bl
static constexpr int SMEM_BYTES = 2 * STAGE_BYTES;  // 147456

// Load one 128x64 bf16 K-major tile into smem (row stride SA). 256 threads, 16B chunks.
__device__ __forceinline__ void load_tile(uint32_t sdst, const __nv_bfloat16* __restrict__ g,
                                          int ldg, int tid) {
#pragma unroll
    for (int i = 0; i < 4; i++) {
        int c = tid + i * 256;
        int row = c >> 3, col = (c & 7) * 8;
        cp16(sdst + (uint32_t)(row * SA + col) * 2, g + (size_t)row * ldg + col);
    }
}

__device__ __forceinline__ void load_stage(uint32_t sbase, int stage,
    const __nv_bfloat16* Ah, const __nv_bfloat16* Al, int ldga,
    const __nv_bfloat16* Bh, const __nv_bfloat16* Bl, int ldgb,
    int kt, int tid)
{
    uint32_t sb = sbase + stage * STAGE_BYTES;
    const __nv_bfloat16* pAh = Ah + kt * 64;
    const __nv_bfloat16* pAl = Al + kt * 64;
    const __nv_bfloat16* pBh = Bh + kt * 64;
    const __nv_bfloat16* pBl = Bl + kt * 64;
    load_tile(sb + 0 * TILE_BYTES, pAh, ldga, tid);
    load_tile(sb + 1 * TILE_BYTES, pAl, ldga, tid);
    load_tile(sb + 2 * TILE_BYTES, pBh, ldgb, tid);
    load_tile(sb + 3 * TILE_BYTES, pBl, ldgb, tid);
}

// One K=64 stage of MMAs for a 32x64 warp tile, 3-term split.
__device__ __forceinline__ void stage_mma(float (&acc)[2][8][4], uint32_t sb,
                                          int warp_m, int warp_n, int lane) {
    uint32_t sAh = sb, sAl = sb + TILE_BYTES, sBh = sb + 2*TILE_BYTES, sBl = sb + 3*TILE_BYTES;
    int lrow = lane & 15;
    int lk   = (lane >> 4) * 8;
#pragma unroll
    for (int ks = 0; ks < 4; ks++) {
        int k = ks * 16 + lk;
        uint32_t ah[2][4], al[2][4], bh[4][4], bl[4][4];
#pragma unroll
        for (int mi = 0; mi < 2; mi++) {
            uint32_t off = (uint32_t)((warp_m * 32 + mi * 16 + lrow) * SA + k) * 2;
            ldsm_x4(ah[mi], sAh + off);
            ldsm_x4(al[mi], sAl + off);
        }
#pragma unroll
        for (int gj = 0; gj < 4; gj++) {
            uint32_t off = (uint32_t)((warp_n * 64 + gj * 16 + lrow) * SA + k) * 2;
            ldsm_x4(bh[gj], sBh + off);
            ldsm_x4(bl[gj], sBl + off);
        }
#pragma unroll
        for (int mi = 0; mi < 2; mi++)
#pragma unroll
        for (int gj = 0; gj < 4; gj++)
#pragma unroll
        for (int hh = 0; hh < 2; hh++) {
            int nj = gj * 2 + hh;
            mma16816(acc[mi][nj], ah[mi], bh[gj][hh], bh[gj][2 + hh]);
            mma16816(acc[mi][nj], ah[mi], bl[gj][hh], bl[gj][2 + hh]);
            mma16816(acc[mi][nj], al[mi], bh[gj][hh], bh[gj][2 + hh]);
        }
    }
}

// Full pipelined GEMM over nk K-stages of 64.
__device__ __forceinline__ void run_gemm(uint32_t sbase, float (&acc)[2][8][4],
    const __nv_bfloat16* Ah, const __nv_bfloat16* Al, int ldga,
    const __nv_bfloat16* Bh, const __nv_bfloat16* Bl, int ldgb,
    int nk, int tid, int warp_m, int warp_n, int lane)
{
    load_stage(sbase, 0, Ah, Al, ldga, Bh, Bl, ldgb, 0, tid);
    CP_COMMIT();
    for (int kt = 0; kt < nk; kt++) {
        if (kt + 1 < nk) {
            load_stage(sbase, (kt + 1) & 1, Ah, Al, ldga, Bh, Bl, ldgb, kt + 1, tid);
            CP_COMMIT();
            CP_WAIT(1);
        } else {
            CP_WAIT(0);
        }
        __syncthreads();
        stage_mma(acc, sbase + (kt & 1) * STAGE_BYTES, warp_m, warp_n, lane);
        __syncthreads();
    }
}

__device__ __forceinline__ float silu(float a) {
    return a / (1.0f + __expf(-a));
}

// ---------------- fused GLU kernel ----------------
__global__ void __launch_bounds__(256, 1) glu_kernel() {
    extern __shared__ char smem[];
    uint32_t sbase = smem_u32(smem);
    int tid = threadIdx.x, lane = tid & 31, wid = tid >> 5;
    int warp_m = wid & 3, warp_n = wid >> 2;
    int e = blockIdx.z, m0 = blockIdx.y * 128, f0 = blockIdx.x * 128;

    // acc2 = x @ v1^T (K = 1024)
    float acc2[2][8][4];
#pragma unroll
    for (int i = 0; i < 2; i++)
#pragma unroll
        for (int j = 0; j < 8; j++)
#pragma unroll
            for (int k = 0; k < 4; k++) acc2[i][j][k] = 0.f;
    run_gemm(sbase, acc2,
             g_x_hi + (size_t)(e * T_ + m0) * H_, g_x_lo + (size_t)(e * T_ + m0) * H_, H_,
             g_v1_hi + ((size_t)e * F_ + f0) * H_, g_v1_lo + ((size_t)e * F_ + f0) * H_, H_,
             H_ / 64, tid, warp_m, warp_n, lane);

    // acc1 = acts @ wup^T (K = 256)
    float acc1[2][8][4];
#pragma unroll
    for (int i = 0; i < 2; i++)
#pragma unroll
        for (int j = 0; j < 8; j++)
#pragma unroll
            for (int k = 0; k < 4; k++) acc1[i][j][k] = 0.f;
    run_gemm(sbase, acc1,
             g_a_hi + (size_t)(e * T_ + m0) * DL_, g_a_lo + (size_t)(e * T_ + m0) * DL_, DL_,
             g_wup_hi + ((size_t)e * F_ + f0) * DL_, g_wup_lo + ((size_t)e * F_ + f0) * DL_, DL_,
             DL_ / 64, tid, warp_m, warp_n, lane);

    // epilogue: h = silu(acc1) * acc2  -> split bf16 hi/lo
    int gid = lane >> 2, q = lane & 3;
#pragma unroll
    for (int mi = 0; mi < 2; mi++)
#pragma unroll
    for (int nj = 0; nj < 8; nj++) {
        int m = m0 + warp_m * 32 + mi * 16 + gid;
        int n = f0 + warp_n * 64 + nj * 8 + q * 2;
        float s0 = silu(acc1[mi][nj][0]) * acc2[mi][nj][0];
        float s1 = silu(acc1[mi][nj][1]) * acc2[mi][nj][1];
        float s2 = silu(acc1[mi][nj][2]) * acc2[mi][nj][2];
        float s3 = silu(acc1[mi][nj][3]) * acc2[mi][nj][3];
        __nv_bfloat16 h0,l0,h1,l1,h2,l2,h3,l3;
        split1(s0,h0,l0); split1(s1,h1,l1); split1(s2,h2,l2); split1(s3,h3,l3);
        size_t off0 = ((size_t)(e * T_ + m)) * F_ + n;
        size_t off1 = ((size_t)(e * T_ + m + 8)) * F_ + n;
        *reinterpret_cast<uint32_t*>(g_h_hi + off0) = pack_bf2(h0, h1);
        *reinterpret_cast<uint32_t*>(g_h_lo + off0) = pack_bf2(l0, l1);
        *reinterpret_cast<uint32_t*>(g_h_hi + off1) = pack_bf2(h2, h3);
        *reinterpret_cast<uint32_t*>(g_h_lo + off1) = pack_bf2(l2, l3);
    }
}

// ---------------- GEMM3: out = h @ w2 (K = 4096) ----------------
__global__ void __launch_bounds__(256, 1) gemm3_kernel(float* __restrict__ out) {
    extern __shared__ char smem[];
    uint32_t sbase = smem_u32(smem);
    int tid = threadIdx.x, lane = tid & 31, wid = tid >> 5;
    int warp_m = wid & 3, warp_n = wid >> 2;
    int e = blockIdx.z, m0 = blockIdx.y * 128, n0 = blockIdx.x * 128;

    float acc[2][8][4];
#pragma unroll
    for (int i = 0; i < 2; i++)
#pragma unroll
        for (int j = 0; j < 8; j++)
#pragma unroll
            for (int k = 0; k < 4; k++) acc[i][j][k] = 0.f;
    run_gemm(sbase, acc,
             g_h_hi + (size_t)(e * T_ + m0) * F_, g_h_lo + (size_t)(e * T_ + m0) * F_, F_,
             g_w2t_hi + ((size_t)e * H_ + n0) * F_, g_w2t_lo + ((size_t)e * H_ + n0) * F_, F_,
             F_ / 64, tid, warp_m, warp_n, lane);

    int gid = lane >> 2, q = lane & 3;
#pragma unroll
    for (int mi = 0; mi < 2; mi++)
#pragma unroll
    for (int nj = 0; nj < 8; nj++) {
        int m = m0 + warp_m * 32 + mi * 16 + gid;
        int n = n0 + warp_n * 64 + nj * 8 + q * 2;
        size_t off0 = ((size_t)(e * T_ + m)) * H_ + n;
        size_t off1 = ((size_t)(e * T_ + m + 8)) * H_ + n;
        float2 v0 = make_float2(acc[mi][nj][0], acc[mi][nj][1]);
        float2 v1 = make_float2(acc[mi][nj][2], acc[mi][nj][3]);
        *reinterpret_cast<float2*>(out + off0) = v0;
        *reinterpret_cast<float2*>(out + off1) = v1;
    }
}

// ---------------- launch ----------------
extern "C" void kernel_launch(void* const* d_in, const int* in_sizes, int n_in,
                              void* d_out, int out_size) {
    const float* x    = (const float*)d_in[0];  // [8192, 1024]
    const float* acts = (const float*)d_in[1];  // [8192, 256]
    const float* wup  = (const float*)d_in[2];  // [8, 4096, 256]
    const float* v1   = (const float*)d_in[3];  // [8, 4096, 1024]
    const float* w2   = (const float*)d_in[4];  // [8, 4096, 1024]
    float* out = (float*)d_out;                 // [8192, 1024]

    cudaFuncSetAttribute(glu_kernel, cudaFuncAttributeMaxDynamicSharedMemorySize, SMEM_BYTES);
    cudaFuncSetAttribute(gemm3_kernel, cudaFuncAttributeMaxDynamicSharedMemorySize, SMEM_BYTES);

    // conversions
    {
        int n;
        n = NTOK * H_;        split_convert<<<n / 4 / 256, 256>>>(x,    0, n);
        n = NTOK * DL_;       split_convert<<<n / 4 / 256, 256>>>(acts, 1, n);
        n = E_ * F_ * DL_;    split_convert<<<n / 4 / 256, 256>>>(wup,  2, n);
        n = E_ * F_ * H_;     split_convert<<<n / 4 / 256, 256>>>(v1,   3, n);
        dim3 tg(F_ / 32, H_ / 32, E_);
        transpose_convert_w2<<<tg, dim3(32, 8)>>>(w2);
    }

    // fused GLU: grid over (f tiles, token tiles, experts)
    {
        dim3 grid(F_ / 128, T_ / 128, E_);
        glu_kernel<<<grid, 256, SMEM_BYTES>>>();
    }

    // out = h @ w2
    {
        dim3 grid(H_ / 128, T_ / 128, E_);
        gemm3_kernel<<<grid, 256, SMEM_BYTES>>>(out);
    }
}